// round 1
// baseline (speedup 1.0000x reference)
#include <cuda_runtime.h>

// Scratch accumulators (one per channel) — __device__ globals, no allocation.
__device__ double g_acc[2];

static const int T_LEN = 60000;
static const int T4    = 15000;   // float4 groups per row
static const int ROWS  = 512;     // B*C = 256*2

__global__ void zero_acc_kernel() {
    g_acc[0] = 0.0;
    g_acc[1] = 0.0;
}

// 7-tap symmetric circular conv coefficients (exact closed form of the 4 roll-adds)
//   offsets -3..3 : 1/8, 5/16, 21/32, 85/64, 21/32, 5/16, 1/8
__global__ __launch_bounds__(256) void bce_main_kernel(
    const float* __restrict__ inp,
    const float* __restrict__ tgt)
{
    const int row = blockIdx.y;                                // 0..511 ; channel = row & 1
    const int j   = blockIdx.x * blockDim.x + threadIdx.x;     // float4 index within row

    float local = 0.0f;
    if (j < T4) {
        const float4* p4 = reinterpret_cast<const float4*>(inp + (size_t)row * T_LEN);
        const float4* t4 = reinterpret_cast<const float4*>(tgt + (size_t)row * T_LEN);

        const int jm = (j == 0)      ? (T4 - 1) : j - 1;       // circular wrap (group level)
        const int jp = (j == T4 - 1) ? 0        : j + 1;

        const float4 tm = __ldg(t4 + jm);
        const float4 tc = __ldg(t4 + j);
        const float4 tp = __ldg(t4 + jp);
        const float4 p  = __ldg(p4 + j);

        // target window covering element indices 4j-3 .. 4j+6
        float t[10] = { tm.y, tm.z, tm.w,
                        tc.x, tc.y, tc.z, tc.w,
                        tp.x, tp.y, tp.z };
        float pv[4] = { p.x, p.y, p.z, p.w };

        const float c0 = 1.328125f;   // 85/64
        const float c1 = 0.65625f;    // 21/32
        const float c2 = 0.3125f;     // 5/16
        const float c3 = 0.125f;      // 1/8

        #pragma unroll
        for (int k = 0; k < 4; ++k) {
            float v = c0 * t[k + 3]
                    + c1 * (t[k + 2] + t[k + 4])
                    + c2 * (t[k + 1] + t[k + 5])
                    + c3 * (t[k]     + t[k + 6]);
            float ta = fminf(v, 1.0f);

            float pk = pv[k];
            float lp = fmaxf(__logf(pk),        -100.0f);
            float lq = fmaxf(__logf(1.0f - pk), -100.0f);
            // bce = -(ta*lp + (1-ta)*lq) = -(lq + ta*(lp - lq))
            local -= fmaf(ta, lp - lq, lq);
        }
    }

    // Block reduction in double (channel is uniform per block: one row per blockIdx.y)
    double d = (double)local;
    #pragma unroll
    for (int off = 16; off > 0; off >>= 1)
        d += __shfl_down_sync(0xffffffffu, d, off);

    __shared__ double sw[8];
    const int lane = threadIdx.x & 31;
    const int w    = threadIdx.x >> 5;
    if (lane == 0) sw[w] = d;
    __syncthreads();
    if (w == 0) {
        d = (lane < 8) ? sw[lane] : 0.0;
        #pragma unroll
        for (int off = 4; off > 0; off >>= 1)
            d += __shfl_down_sync(0xffu, d, off);
        if (lane == 0) atomicAdd(&g_acc[row & 1], d);
    }
}

__global__ void finalize_kernel(float* out) {
    const double num = 256.0 * 60000.0;
    const double tb  = 0.5 * g_acc[0] / num;   // total_beat (alpha=0.5 makes pos/neg split a no-op)
    const double td  = 0.5 * g_acc[1] / num;   // total_down
    out[0] = (float)(tb + td);                 // total
    out[1] = (float)tb;
    out[2] = (float)td;
}

extern "C" void kernel_launch(void* const* d_in, const int* in_sizes, int n_in,
                              void* d_out, int out_size)
{
    const float* inp = (const float*)d_in[0];
    const float* tgt = (const float*)d_in[1];
    float* out = (float*)d_out;

    zero_acc_kernel<<<1, 1>>>();

    dim3 block(256);
    dim3 grid((T4 + 255) / 256, ROWS);   // (59, 512)
    bce_main_kernel<<<grid, block>>>(inp, tgt);

    finalize_kernel<<<1, 1>>>(out);
}